// round 7
// baseline (speedup 1.0000x reference)
#include <cuda_runtime.h>
#include <cuda_bf16.h>
#include <cstdint>

// Chamfer loss, B=4, N=M=8192, D=3.
//   dist(i,j) = ||a_i||^2 + ( ||b_j||^2 - 2 a_i . b_j )
// Pre-pack B-set as quads {-2b0[4], -2b1[4], -2b2[4], ||b||^2[4]} (64B per 4 pts).
// Main kernel: thread holds 4 A points; per B-group: 4x LDS.128 (broadcast) +
// 24 packed f32x2 FFMA + 16 FMNMX -> fma-pipe bound at the 1.5 FFMA2 + 1 FMNMX
// per-pair floor. Both directions + 16-way B-split in one 2048-block launch;
// slice mins merged via atomicMin on nonneg-float-as-uint (order-independent
// => deterministic). 3 launches total: pack(+init), chamfer, fused reduce
// (last-block pattern, deterministic fixed-order final sum).
// R6 fix: pack_kernel min-init was writing uint2 per thread (2x coverage,
// 32KB OOB for the y-half); now exactly one uint per (which, idx).

#define BATCH   4
#define NPTS    8192
#define GROUPS  (NPTS / 4)       // 2048
#define SB      16               // B slices
#define SLICE_G (GROUPS / SB)    // 128 groups = 512 B points = 8KB packed
#define BLK     128
#define APT     4                // A points per thread
#define ACHUNK  (BLK * APT)      // 512
#define NCHUNK  (NPTS / ACHUNK)  // 16
#define NMINS   (2 * BATCH * NPTS)   // 65536
#define RBLKS   64

__device__ float    g_packedX[BATCH * GROUPS * 16];
__device__ float    g_packedY[BATCH * GROUPS * 16];
__device__ unsigned g_minbits[NMINS];
__device__ float    g_partial[RBLKS];
__device__ unsigned g_ticket;

#define FMA_F32X2(d, a, b, c) \
    asm("fma.rn.f32x2 %0, %1, %2, %3;" : "=l"(d) : "l"(a), "l"(b), "l"(c))
#define PACK2_SAME(out, r) \
    asm("mov.b64 %0, {%1, %1};" : "=l"(out) : "r"(r))
#define UNPACK_F32X2(lo, hi, in) \
    asm("mov.b64 {%0, %1}, %2;" : "=r"(lo), "=r"(hi) : "l"(in))

// One launch: blocks [0,128) pack x (and init minbits[0, 32768)),
//             blocks [128,256) pack y (and init minbits[32768, 65536)).
// Block 0 thread 0 also resets the reduce ticket (graph-replay safe).
__global__ __launch_bounds__(256) void pack_kernel(
    const float* __restrict__ x, const float* __restrict__ y)
{
    if (blockIdx.x == 0 && threadIdx.x == 0) g_ticket = 0;

    int which = (blockIdx.x >= 128);
    int idx = (blockIdx.x & 127) * 256 + threadIdx.x;   // 0 .. BATCH*NPTS-1
    if (idx >= BATCH * NPTS) return;

    // exactly one min slot per (which, idx)
    g_minbits[which * (BATCH * NPTS) + idx] = 0x7F800000u;

    const float* __restrict__ src = which ? y : x;
    float* __restrict__ dst = which ? g_packedY : g_packedX;

    int b = idx >> 13;
    int j = idx & (NPTS - 1);
    float s0 = src[(size_t)idx * 3 + 0];
    float s1 = src[(size_t)idx * 3 + 1];
    float s2 = src[(size_t)idx * 3 + 2];
    int g = j >> 2, l = j & 3;
    float* base = dst + ((size_t)(b * GROUPS + g)) * 16;
    base[0  + l] = -2.0f * s0;
    base[4  + l] = -2.0f * s1;
    base[8  + l] = -2.0f * s2;
    base[12 + l] = s0 * s0 + s1 * s1 + s2 * s2;
}

__global__ __launch_bounds__(BLK) void chamfer_kernel(
    const float* __restrict__ x, const float* __restrict__ y)
{
    __shared__ float4 sy[SLICE_G * 4];               // 8 KB

    int dir   = blockIdx.z >> 4;                     // 0: x->y, 1: y->x
    int slice = blockIdx.z & (SB - 1);
    int b     = blockIdx.y;
    int chunk = blockIdx.x;

    const float* __restrict__ A       = dir ? y : x;
    const float* __restrict__ packedB = dir ? g_packedX : g_packedY;

    // Load this block's B-slice into smem (512 float4, 128 threads -> 4 each)
    const float4* gsrc = (const float4*)(packedB +
        ((size_t)(b * GROUPS + slice * SLICE_G)) * 16);
    #pragma unroll
    for (int k = 0; k < SLICE_G * 4 / BLK; ++k)
        sy[threadIdx.x + k * BLK] = gsrc[threadIdx.x + k * BLK];

    // Load 4 consecutive A points (48 bytes, 16B-aligned) as 3 float4
    int i0 = chunk * ACHUNK + threadIdx.x * APT;
    const float4* ap = (const float4*)(A + ((size_t)b * NPTS + i0) * 3);
    float4 q0 = ap[0], q1 = ap[1], q2 = ap[2];

    float a0c[APT] = {q0.x, q0.w, q1.z, q2.y};
    float a1c[APT] = {q0.y, q1.x, q1.w, q2.z};
    float a2c[APT] = {q0.z, q1.y, q2.x, q2.w};

    unsigned long long ax[APT], ay[APT], az[APT];
    float a2n[APT];
    #pragma unroll
    for (int j = 0; j < APT; ++j) {
        PACK2_SAME(ax[j], __float_as_uint(a0c[j]));
        PACK2_SAME(ay[j], __float_as_uint(a1c[j]));
        PACK2_SAME(az[j], __float_as_uint(a2c[j]));
        a2n[j] = a0c[j]*a0c[j] + a1c[j]*a1c[j] + a2c[j]*a2c[j];
    }

    float m[APT][4];
    #pragma unroll
    for (int j = 0; j < APT; ++j)
        m[j][0] = m[j][1] = m[j][2] = m[j][3] = 1e30f;

    __syncthreads();

    const ulonglong2* sp = (const ulonglong2*)sy;
    #pragma unroll 2
    for (int g = 0; g < SLICE_G; ++g) {
        ulonglong2 p0 = sp[g * 4 + 0];   // {-2b0 ab, -2b0 cd}
        ulonglong2 p1 = sp[g * 4 + 1];   // {-2b1 ab, -2b1 cd}
        ulonglong2 p2 = sp[g * 4 + 2];   // {-2b2 ab, -2b2 cd}
        ulonglong2 p3 = sp[g * 4 + 3];   // {n   ab,  n   cd}

        #pragma unroll
        for (int j = 0; j < APT; ++j) {
            unsigned long long tab, tcd;
            FMA_F32X2(tab, ax[j], p0.x, p3.x);
            FMA_F32X2(tcd, ax[j], p0.y, p3.y);
            FMA_F32X2(tab, ay[j], p1.x, tab);
            FMA_F32X2(tcd, ay[j], p1.y, tcd);
            FMA_F32X2(tab, az[j], p2.x, tab);
            FMA_F32X2(tcd, az[j], p2.y, tcd);

            unsigned lo, hi;
            UNPACK_F32X2(lo, hi, tab);
            m[j][0] = fminf(m[j][0], __uint_as_float(lo));
            m[j][1] = fminf(m[j][1], __uint_as_float(hi));
            UNPACK_F32X2(lo, hi, tcd);
            m[j][2] = fminf(m[j][2], __uint_as_float(lo));
            m[j][3] = fminf(m[j][3], __uint_as_float(hi));
        }
    }

    // Fold, add ||a||^2, clamp >=0 (so uint-min ordering is exact), merge slices
    unsigned base = (unsigned)((dir * BATCH + b) * NPTS + i0);
    #pragma unroll
    for (int j = 0; j < APT; ++j) {
        float mm  = fminf(fminf(m[j][0], m[j][1]), fminf(m[j][2], m[j][3]));
        float val = fmaxf(a2n[j] + mm, 0.0f);
        atomicMin(&g_minbits[base + j], __float_as_uint(val));
    }
}

// Fused reduction: 64 blocks x 1024 values; last-arriving block folds the 64
// partials (fixed index order -> deterministic) and writes the mean.
__global__ __launch_bounds__(256) void reduce_kernel(float* __restrict__ out)
{
    __shared__ float s[256];
    __shared__ bool  islast;

    const uint4* src = (const uint4*)g_minbits;
    uint4 v = src[blockIdx.x * 256 + threadIdx.x];
    float sum = __uint_as_float(v.x) + __uint_as_float(v.y)
              + __uint_as_float(v.z) + __uint_as_float(v.w);
    s[threadIdx.x] = sum;
    __syncthreads();
    #pragma unroll
    for (int st = 128; st > 0; st >>= 1) {
        if (threadIdx.x < st) s[threadIdx.x] += s[threadIdx.x + st];
        __syncthreads();
    }
    if (threadIdx.x == 0) {
        g_partial[blockIdx.x] = s[0];
        __threadfence();
        unsigned t = atomicAdd(&g_ticket, 1u);
        islast = (t == RBLKS - 1);
    }
    __syncthreads();

    if (islast) {
        float p = (threadIdx.x < RBLKS) ? g_partial[threadIdx.x] : 0.0f;
        s[threadIdx.x] = p;
        __syncthreads();
        #pragma unroll
        for (int st = 128; st > 0; st >>= 1) {
            if (threadIdx.x < st) s[threadIdx.x] += s[threadIdx.x + st];
            __syncthreads();
        }
        if (threadIdx.x == 0)
            out[0] = s[0] * (1.0f / (float)(BATCH * NPTS));
    }
}

extern "C" void kernel_launch(void* const* d_in, const int* in_sizes, int n_in,
                              void* d_out, int out_size)
{
    (void)in_sizes; (void)n_in; (void)out_size;
    const float* x = (const float*)d_in[0];
    const float* y = (const float*)d_in[1];
    float* out = (float*)d_out;

    pack_kernel<<<256, 256>>>(x, y);                // pack both sets + init mins + ticket

    dim3 grid(NCHUNK, BATCH, 2 * SB);               // 16 x 4 x 32 = 2048 blocks
    chamfer_kernel<<<grid, BLK>>>(x, y);

    reduce_kernel<<<RBLKS, 256>>>(out);
}